// round 1
// baseline (speedup 1.0000x reference)
#include <cuda_runtime.h>
#include <cuda_bf16.h>
#include <cstdint>

// Problem constants (fixed by the reference)
#define N_NODES 500000
#define N_EDGES 1000000
#define D       32
#define CD      64
#define HID     128
#define NCEN    20
#define RBF_GAMMA 10.0f

#define FULLMASK 0xffffffffu

// ---------------------------------------------------------------------------
// Kernel 1: zero the aggregation buffer (we reuse d_out as agg scratch)
// ---------------------------------------------------------------------------
__global__ void zero_kernel(float4* __restrict__ p, int n4) {
    int i = blockIdx.x * blockDim.x + threadIdx.x;
    int stride = gridDim.x * blockDim.x;
    float4 z = make_float4(0.f, 0.f, 0.f, 0.f);
    for (; i < n4; i += stride) p[i] = z;
}

// ---------------------------------------------------------------------------
// Kernel 2: per-edge bond embedding + gather + scatter-add (vector atomics)
// One warp per edge (grid-stride). Lane l owns channels {l, l+32}.
// ---------------------------------------------------------------------------
__global__ void edge_kernel(
    const float* __restrict__ atom,
    const int*   __restrict__ src,  const int* __restrict__ dst,
    const int*   __restrict__ rdir, const int* __restrict__ rtype, const int* __restrict__ rring,
    const int*   __restrict__ pdir, const int* __restrict__ ptype, const int* __restrict__ pring,
    const float* __restrict__ rlen, const float* __restrict__ plen,
    const float* __restrict__ emb_dir, const float* __restrict__ emb_type,
    const float* __restrict__ emb_ring,
    const float* __restrict__ rbf_W, const float* __restrict__ rbf_b,
    float* __restrict__ agg)
{
    const int l = threadIdx.x & 31;
    const int warp = (blockIdx.x * blockDim.x + threadIdx.x) >> 5;
    const int nwarps = (gridDim.x * blockDim.x) >> 5;

    // Register-resident column of rbf_W for this lane: rbf_W[k][l]
    float wcol[NCEN];
#pragma unroll
    for (int k = 0; k < NCEN; k++) wcol[k] = rbf_W[k * D + l];
    const float rbfb = rbf_b[l];
    const float cl = 0.1f * (float)l;  // RBF center for lane l (lanes >= 20 unused)

    for (int e = warp; e < N_EDGES; e += nwarps) {
        const int s = src[e];
        const int dn = dst[e];
        const float rl = rlen[e];
        const float pl = plen[e];

        // one exp per lane per side; lanes 20..31 produce harmless ~0 values
        float drr = rl - cl;
        float er = __expf(-RBF_GAMMA * drr * drr);
        float dpp = pl - cl;
        float ep = __expf(-RBF_GAMMA * dpp * dpp);

        float re = emb_dir[rdir[e] * D + l] + emb_type[rtype[e] * D + l]
                 + emb_ring[rring[e] * D + l] + rbfb;
        float pe = emb_dir[pdir[e] * D + l] + emb_type[ptype[e] * D + l]
                 + emb_ring[pring[e] * D + l] + rbfb;

#pragma unroll
        for (int k = 0; k < NCEN; k++) {
            re = fmaf(__shfl_sync(FULLMASK, er, k), wcol[k], re);
            pe = fmaf(__shfl_sync(FULLMASK, ep, k), wcol[k], pe);
        }

        // msg channels: [0..31] = atom[src][c] + r_e ; [32..63] = atom[src][c] + (p_e - r_e)
        const size_t arow = (size_t)s * CD;
        float m0 = atom[arow + l] + re;
        float m1 = atom[arow + 32 + l] + (pe - re);

        // Repack so lane l<16 holds channels 4l..4l+3 -> one red.global.add.v4.f32
        float v0, v1, v2, v3;
        {
            int c0 = 4 * l;
            float a0 = __shfl_sync(FULLMASK, m0, (c0 + 0) & 31);
            float b0 = __shfl_sync(FULLMASK, m1, (c0 + 0) & 31);
            float a1 = __shfl_sync(FULLMASK, m0, (c0 + 1) & 31);
            float b1 = __shfl_sync(FULLMASK, m1, (c0 + 1) & 31);
            float a2 = __shfl_sync(FULLMASK, m0, (c0 + 2) & 31);
            float b2 = __shfl_sync(FULLMASK, m1, (c0 + 2) & 31);
            float a3 = __shfl_sync(FULLMASK, m0, (c0 + 3) & 31);
            float b3 = __shfl_sync(FULLMASK, m1, (c0 + 3) & 31);
            bool lo = (l < 8);
            v0 = lo ? a0 : b0;
            v1 = lo ? a1 : b1;
            v2 = lo ? a2 : b2;
            v3 = lo ? a3 : b3;
        }
        if (l < 16) {
            float* p = agg + (size_t)dn * CD + 4 * l;
            asm volatile("red.global.add.v4.f32 [%0], {%1,%2,%3,%4};"
                         :: "l"(p), "f"(v0), "f"(v1), "f"(v2), "f"(v3)
                         : "memory");
        }
    }
}

// ---------------------------------------------------------------------------
// Kernel 3: per-node MLP, in place on the agg buffer.
// One warp per node. Lane l computes h[4l..4l+3] then out[2l..2l+1].
// Weights staged in dynamic smem.
// ---------------------------------------------------------------------------
__global__ void mlp_kernel(
    float* __restrict__ inout,           // [N_NODES, CD], agg in, out out
    const float* __restrict__ W1,        // [CD, HID]
    const float* __restrict__ b1,        // [HID]
    const float* __restrict__ W2,        // [HID, CD]
    const float* __restrict__ b2)        // [CD]
{
    extern __shared__ float sm[];
    float* sW1 = sm;                         // 64*128
    float* sW2 = sW1 + CD * HID;             // 128*64
    float* sb1 = sW2 + HID * CD;             // 128
    float* sb2 = sb1 + HID;                  // 64

    const int tid = threadIdx.x;
    for (int i = tid; i < CD * HID; i += blockDim.x) {
        sW1[i] = W1[i];
        sW2[i] = W2[i];
    }
    for (int i = tid; i < HID; i += blockDim.x) sb1[i] = b1[i];
    for (int i = tid; i < CD;  i += blockDim.x) sb2[i] = b2[i];
    __syncthreads();

    const int l = tid & 31;
    const int warp = (blockIdx.x * (blockDim.x >> 5)) + (tid >> 5);
    const int nwarps = gridDim.x * (blockDim.x >> 5);

    for (int n = warp; n < N_NODES; n += nwarps) {
        float* row = inout + (size_t)n * CD;
        const float a0 = row[l];
        const float a1 = row[32 + l];

        // stage 1: h[4l+k] = relu(b1 + sum_j a[j] * W1[j][4l+k])
        float h0 = sb1[4 * l + 0];
        float h1 = sb1[4 * l + 1];
        float h2 = sb1[4 * l + 2];
        float h3 = sb1[4 * l + 3];

#pragma unroll 8
        for (int j = 0; j < 32; j++) {
            float aj = __shfl_sync(FULLMASK, a0, j);
            float4 w = *reinterpret_cast<const float4*>(&sW1[j * HID + 4 * l]);
            h0 = fmaf(aj, w.x, h0);
            h1 = fmaf(aj, w.y, h1);
            h2 = fmaf(aj, w.z, h2);
            h3 = fmaf(aj, w.w, h3);
        }
#pragma unroll 8
        for (int j = 0; j < 32; j++) {
            float aj = __shfl_sync(FULLMASK, a1, j);
            float4 w = *reinterpret_cast<const float4*>(&sW1[(j + 32) * HID + 4 * l]);
            h0 = fmaf(aj, w.x, h0);
            h1 = fmaf(aj, w.y, h1);
            h2 = fmaf(aj, w.z, h2);
            h3 = fmaf(aj, w.w, h3);
        }
        float hv[4];
        hv[0] = fmaxf(h0, 0.f);
        hv[1] = fmaxf(h1, 0.f);
        hv[2] = fmaxf(h2, 0.f);
        hv[3] = fmaxf(h3, 0.f);

        // stage 2: out[2l+m] = relu(b2 + sum_i h[i] * W2[i][2l+m])
        float o0 = sb2[2 * l + 0];
        float o1 = sb2[2 * l + 1];
#pragma unroll 4
        for (int i0 = 0; i0 < HID; i0 += 4) {
            int srcl = i0 >> 2;  // h[i0+k] lives in lane (i0>>2), component k
#pragma unroll
            for (int k = 0; k < 4; k++) {
                float hi = __shfl_sync(FULLMASK, hv[k], srcl);
                float2 w2 = *reinterpret_cast<const float2*>(&sW2[(i0 + k) * CD + 2 * l]);
                o0 = fmaf(hi, w2.x, o0);
                o1 = fmaf(hi, w2.y, o1);
            }
        }
        float2 res = make_float2(fmaxf(o0, 0.f), fmaxf(o1, 0.f));
        *reinterpret_cast<float2*>(&row[2 * l]) = res;
    }
}

// ---------------------------------------------------------------------------
// Launch
// Inputs (metadata order):
//  0 atom_repr [N,64] f32     1 src [E] i32      2 dst [E] i32
//  3 r_dir     4 r_type       5 r_ring           6 p_dir
//  7 p_type    8 p_ring       9 r_len f32       10 p_len f32
// 11 emb_dir [8,32]          12 emb_type [16,32] 13 emb_ring [4,32]
// 14 rbf_W [20,32]           15 rbf_b [32]
// 16 W1 [64,128]             17 b1 [128]
// 18 W2 [128,64]             19 b2 [64]
// Output: [N,64] f32
// ---------------------------------------------------------------------------
extern "C" void kernel_launch(void* const* d_in, const int* in_sizes, int n_in,
                              void* d_out, int out_size) {
    const float* atom     = (const float*)d_in[0];
    const int*   src      = (const int*)d_in[1];
    const int*   dst      = (const int*)d_in[2];
    const int*   rdir     = (const int*)d_in[3];
    const int*   rtype    = (const int*)d_in[4];
    const int*   rring    = (const int*)d_in[5];
    const int*   pdir     = (const int*)d_in[6];
    const int*   ptype    = (const int*)d_in[7];
    const int*   pring    = (const int*)d_in[8];
    const float* rlen     = (const float*)d_in[9];
    const float* plen     = (const float*)d_in[10];
    const float* emb_dir  = (const float*)d_in[11];
    const float* emb_type = (const float*)d_in[12];
    const float* emb_ring = (const float*)d_in[13];
    const float* rbf_W    = (const float*)d_in[14];
    const float* rbf_b    = (const float*)d_in[15];
    const float* W1       = (const float*)d_in[16];
    const float* b1       = (const float*)d_in[17];
    const float* W2       = (const float*)d_in[18];
    const float* b2       = (const float*)d_in[19];
    float* out = (float*)d_out;

    // 1) zero the agg buffer (= d_out)
    int n4 = (N_NODES * CD) / 4;
    zero_kernel<<<2048, 256>>>((float4*)out, n4);

    // 2) edge scatter
    edge_kernel<<<1480, 256>>>(atom, src, dst, rdir, rtype, rring,
                               pdir, ptype, pring, rlen, plen,
                               emb_dir, emb_type, emb_ring, rbf_W, rbf_b, out);

    // 3) node MLP (in place)
    size_t smem = (size_t)(CD * HID + HID * CD + HID + CD) * sizeof(float);
    cudaFuncSetAttribute(mlp_kernel, cudaFuncAttributeMaxDynamicSharedMemorySize,
                         (int)smem);
    mlp_kernel<<<444, 256, smem>>>(out, W1, b1, W2, b2);
}

// round 2
// speedup vs baseline: 1.6483x; 1.6483x over previous
#include <cuda_runtime.h>
#include <cuda_bf16.h>
#include <cstdint>

// Problem constants (fixed by the reference)
#define N_NODES 500000
#define N_EDGES 1000000
#define D       32
#define CD      64
#define HID     128
#define NCEN    20
#define RBF_GAMMA 10.0f

#define FULLMASK 0xffffffffu

typedef unsigned long long ull;

// ---- packed f32x2 helpers (sm_103a) ---------------------------------------
__device__ __forceinline__ ull ffma2(ull a, ull b, ull c) {
    ull d;
    asm("fma.rn.f32x2 %0, %1, %2, %3;" : "=l"(d) : "l"(a), "l"(b), "l"(c));
    return d;
}
__device__ __forceinline__ ull pack2(float lo, float hi) {
    ull d;
    asm("mov.b64 %0, {%1, %2};" : "=l"(d) : "f"(lo), "f"(hi));
    return d;
}
__device__ __forceinline__ void unpack2(ull v, float& lo, float& hi) {
    asm("mov.b64 {%0, %1}, %2;" : "=f"(lo), "=f"(hi) : "l"(v));
}

// ---------------------------------------------------------------------------
// Kernel 1: zero the aggregation buffer (we reuse d_out as agg scratch)
// ---------------------------------------------------------------------------
__global__ void zero_kernel(float4* __restrict__ p, int n4) {
    int i = blockIdx.x * blockDim.x + threadIdx.x;
    int stride = gridDim.x * blockDim.x;
    float4 z = make_float4(0.f, 0.f, 0.f, 0.f);
    for (; i < n4; i += stride) p[i] = z;
}

// ---------------------------------------------------------------------------
// Kernel 2: per-edge bond embedding + gather + scatter-add (vector atomics)
// One warp per edge (grid-stride). Lane l owns channels {l, l+32}.
// ---------------------------------------------------------------------------
__global__ void edge_kernel(
    const float* __restrict__ atom,
    const int*   __restrict__ src,  const int* __restrict__ dst,
    const int*   __restrict__ rdir, const int* __restrict__ rtype, const int* __restrict__ rring,
    const int*   __restrict__ pdir, const int* __restrict__ ptype, const int* __restrict__ pring,
    const float* __restrict__ rlen, const float* __restrict__ plen,
    const float* __restrict__ emb_dir, const float* __restrict__ emb_type,
    const float* __restrict__ emb_ring,
    const float* __restrict__ rbf_W, const float* __restrict__ rbf_b,
    float* __restrict__ agg)
{
    const int l = threadIdx.x & 31;
    const int warp = (blockIdx.x * blockDim.x + threadIdx.x) >> 5;
    const int nwarps = (gridDim.x * blockDim.x) >> 5;

    // Register-resident column of rbf_W for this lane: rbf_W[k][l]
    float wcol[NCEN];
#pragma unroll
    for (int k = 0; k < NCEN; k++) wcol[k] = rbf_W[k * D + l];
    const float rbfb = rbf_b[l];
    const float cl = 0.1f * (float)l;  // RBF center for lane l (lanes >= 20 unused)

    for (int e = warp; e < N_EDGES; e += nwarps) {
        const int s = src[e];
        const int dn = dst[e];
        const float rl = rlen[e];
        const float pl = plen[e];

        // one exp per lane per side; lanes 20..31 produce harmless ~0 values
        float drr = rl - cl;
        float er = __expf(-RBF_GAMMA * drr * drr);
        float dpp = pl - cl;
        float ep = __expf(-RBF_GAMMA * dpp * dpp);

        float re = emb_dir[rdir[e] * D + l] + emb_type[rtype[e] * D + l]
                 + emb_ring[rring[e] * D + l] + rbfb;
        float pe = emb_dir[pdir[e] * D + l] + emb_type[ptype[e] * D + l]
                 + emb_ring[pring[e] * D + l] + rbfb;

#pragma unroll
        for (int k = 0; k < NCEN; k++) {
            re = fmaf(__shfl_sync(FULLMASK, er, k), wcol[k], re);
            pe = fmaf(__shfl_sync(FULLMASK, ep, k), wcol[k], pe);
        }

        // msg channels: [0..31] = atom[src][c] + r_e ; [32..63] = atom[src][c] + (p_e - r_e)
        const size_t arow = (size_t)s * CD;
        float m0 = atom[arow + l] + re;
        float m1 = atom[arow + 32 + l] + (pe - re);

        // Repack so lane l<16 holds channels 4l..4l+3 -> one red.global.add.v4.f32
        float v0, v1, v2, v3;
        {
            int c0 = 4 * l;
            float a0 = __shfl_sync(FULLMASK, m0, (c0 + 0) & 31);
            float b0 = __shfl_sync(FULLMASK, m1, (c0 + 0) & 31);
            float a1 = __shfl_sync(FULLMASK, m0, (c0 + 1) & 31);
            float b1 = __shfl_sync(FULLMASK, m1, (c0 + 1) & 31);
            float a2 = __shfl_sync(FULLMASK, m0, (c0 + 2) & 31);
            float b2 = __shfl_sync(FULLMASK, m1, (c0 + 2) & 31);
            float a3 = __shfl_sync(FULLMASK, m0, (c0 + 3) & 31);
            float b3 = __shfl_sync(FULLMASK, m1, (c0 + 3) & 31);
            bool lo = (l < 8);
            v0 = lo ? a0 : b0;
            v1 = lo ? a1 : b1;
            v2 = lo ? a2 : b2;
            v3 = lo ? a3 : b3;
        }
        if (l < 16) {
            float* p = agg + (size_t)dn * CD + 4 * l;
            asm volatile("red.global.add.v4.f32 [%0], {%1,%2,%3,%4};"
                         :: "l"(p), "f"(v0), "f"(v1), "f"(v2), "f"(v3)
                         : "memory");
        }
    }
}

// ---------------------------------------------------------------------------
// Kernel 3: per-node MLP, in place on the agg buffer.
// THREAD-per-node: all lanes of a warp share every weight load (LDS
// broadcast, no crossbar pressure), activations + output accumulators live
// in registers, math uses packed fma.rn.f32x2 (2 FMAs / issue slot).
// ---------------------------------------------------------------------------
#define W1T_STRIDE 68   // padded row stride (floats): kills STS conflicts, keeps 16B align

__global__ __launch_bounds__(128) void mlp_kernel(
    float* __restrict__ inout,           // [N_NODES, CD], agg in, out out
    const float* __restrict__ W1,        // [CD, HID]
    const float* __restrict__ b1,        // [HID]
    const float* __restrict__ W2,        // [HID, CD]
    const float* __restrict__ b2)        // [CD]
{
    extern __shared__ float sm[];
    float* sW1T = sm;                          // [HID][W1T_STRIDE] transposed W1
    float* sW2  = sW1T + HID * W1T_STRIDE;     // [HID][CD]
    float* sb1  = sW2 + HID * CD;              // [HID]
    float* sb2  = sb1 + HID;                   // [CD]

    const int tid = threadIdx.x;

    // Load W1 transposed: read coalesced (idx = j*HID + i), scatter to sW1T[i][j].
    for (int idx = tid; idx < CD * HID; idx += blockDim.x) {
        int j = idx >> 7;        // 0..63
        int i = idx & 127;       // 0..127
        sW1T[i * W1T_STRIDE + j] = W1[idx];
    }
    for (int idx = tid; idx < HID * CD; idx += blockDim.x) sW2[idx] = W2[idx];
    if (tid < HID) sb1[tid] = b1[tid];
    if (tid < CD)  sb2[tid] = b2[tid];
    __syncthreads();

    int n = blockIdx.x * blockDim.x + tid;
    if (n >= N_NODES) return;

    float* row = inout + (size_t)n * CD;

    // Load this node's 64 activations as 32 packed f32x2.
    ull a2[32];
    {
        const ulonglong2* ar = reinterpret_cast<const ulonglong2*>(row);
#pragma unroll
        for (int k = 0; k < 16; k++) {
            ulonglong2 v = ar[k];
            a2[2 * k]     = v.x;
            a2[2 * k + 1] = v.y;
        }
    }

    // Output accumulators init = b2 (bit-packed pairs straight from smem).
    ull o2[32];
    {
        const ulonglong2* bp = reinterpret_cast<const ulonglong2*>(sb2);
#pragma unroll
        for (int k = 0; k < 16; k++) {
            ulonglong2 v = bp[k];
            o2[2 * k]     = v.x;
            o2[2 * k + 1] = v.y;
        }
    }

    const ull z2 = pack2(0.f, 0.f);

#pragma unroll 4
    for (int i = 0; i < HID; i++) {
        // h_i = relu(b1[i] + sum_j a[j] * W1[j][i])  — pair over j
        const ulonglong2* w1r =
            reinterpret_cast<const ulonglong2*>(sW1T + i * W1T_STRIDE);
        ull acc0 = z2, acc1 = z2;
#pragma unroll
        for (int p = 0; p < 16; p++) {
            ulonglong2 w = w1r[p];                 // broadcast LDS.128
            acc0 = ffma2(a2[2 * p],     w.x, acc0);
            acc1 = ffma2(a2[2 * p + 1], w.y, acc1);
        }
        float l0, h0, l1, h1;
        unpack2(acc0, l0, h0);
        unpack2(acc1, l1, h1);
        float h = fmaxf((l0 + h0) + (l1 + h1) + sb1[i], 0.f);
        ull hh = pack2(h, h);

        // out[n] += h_i * W2[i][n]  — pair over n
        const ulonglong2* w2r =
            reinterpret_cast<const ulonglong2*>(sW2 + i * CD);
#pragma unroll
        for (int p = 0; p < 16; p++) {
            ulonglong2 w = w2r[p];                 // broadcast LDS.128
            o2[2 * p]     = ffma2(hh, w.x, o2[2 * p]);
            o2[2 * p + 1] = ffma2(hh, w.y, o2[2 * p + 1]);
        }
    }

    // Final relu + store.
    float4* outv = reinterpret_cast<float4*>(row);
#pragma unroll
    for (int k = 0; k < 16; k++) {
        float x0, x1, x2, x3;
        unpack2(o2[2 * k],     x0, x1);
        unpack2(o2[2 * k + 1], x2, x3);
        float4 r;
        r.x = fmaxf(x0, 0.f);
        r.y = fmaxf(x1, 0.f);
        r.z = fmaxf(x2, 0.f);
        r.w = fmaxf(x3, 0.f);
        outv[k] = r;
    }
}

// ---------------------------------------------------------------------------
// Launch
// Inputs (metadata order):
//  0 atom_repr [N,64] f32     1 src [E] i32      2 dst [E] i32
//  3 r_dir     4 r_type       5 r_ring           6 p_dir
//  7 p_type    8 p_ring       9 r_len f32       10 p_len f32
// 11 emb_dir [8,32]          12 emb_type [16,32] 13 emb_ring [4,32]
// 14 rbf_W [20,32]           15 rbf_b [32]
// 16 W1 [64,128]             17 b1 [128]
// 18 W2 [128,64]             19 b2 [64]
// Output: [N,64] f32
// ---------------------------------------------------------------------------
extern "C" void kernel_launch(void* const* d_in, const int* in_sizes, int n_in,
                              void* d_out, int out_size) {
    const float* atom     = (const float*)d_in[0];
    const int*   src      = (const int*)d_in[1];
    const int*   dst      = (const int*)d_in[2];
    const int*   rdir     = (const int*)d_in[3];
    const int*   rtype    = (const int*)d_in[4];
    const int*   rring    = (const int*)d_in[5];
    const int*   pdir     = (const int*)d_in[6];
    const int*   ptype    = (const int*)d_in[7];
    const int*   pring    = (const int*)d_in[8];
    const float* rlen     = (const float*)d_in[9];
    const float* plen     = (const float*)d_in[10];
    const float* emb_dir  = (const float*)d_in[11];
    const float* emb_type = (const float*)d_in[12];
    const float* emb_ring = (const float*)d_in[13];
    const float* rbf_W    = (const float*)d_in[14];
    const float* rbf_b    = (const float*)d_in[15];
    const float* W1       = (const float*)d_in[16];
    const float* b1       = (const float*)d_in[17];
    const float* W2       = (const float*)d_in[18];
    const float* b2       = (const float*)d_in[19];
    float* out = (float*)d_out;

    // 1) zero the agg buffer (= d_out)
    int n4 = (N_NODES * CD) / 4;
    zero_kernel<<<2048, 256>>>((float4*)out, n4);

    // 2) edge scatter
    edge_kernel<<<1480, 256>>>(atom, src, dst, rdir, rtype, rring,
                               pdir, ptype, pring, rlen, plen,
                               emb_dir, emb_type, emb_ring, rbf_W, rbf_b, out);

    // 3) node MLP (in place), thread-per-node
    size_t smem = (size_t)(HID * W1T_STRIDE + HID * CD + HID + CD) * sizeof(float);
    cudaFuncSetAttribute(mlp_kernel, cudaFuncAttributeMaxDynamicSharedMemorySize,
                         (int)smem);
    int blocks = (N_NODES + 127) / 128;
    mlp_kernel<<<blocks, 128, smem>>>(out, W1, b1, W2, b2);
}

// round 3
// speedup vs baseline: 1.8575x; 1.1270x over previous
#include <cuda_runtime.h>
#include <cuda_bf16.h>
#include <cstdint>

// Problem constants (fixed by the reference)
#define N_NODES 500000
#define N_EDGES 1000000
#define D       32
#define CD      64
#define HID     128
#define NCEN    20
#define RBF_GAMMA 10.0f

#define TAB_INTERVALS 2048        // PWL intervals over len in [0,2)
#define TAB_SCALE     1024.0f     // intervals per unit length

#define FULLMASK 0xffffffffu

typedef unsigned long long ull;

// ---- device-global precomputed tables (allowed scratch) --------------------
__device__ float  g_ct[512 * 32];              // combined cat embedding [dir*16+type)*4+ring][ch]
__device__ float4 g_tab[TAB_INTERVALS * 16];   // PWL rbf: per (interval, ch-pair): (v0,v1,dv0,dv1)

// ---- packed f32x2 helpers (sm_103a) ---------------------------------------
__device__ __forceinline__ ull ffma2(ull a, ull b, ull c) {
    ull d;
    asm("fma.rn.f32x2 %0, %1, %2, %3;" : "=l"(d) : "l"(a), "l"(b), "l"(c));
    return d;
}
__device__ __forceinline__ ull pack2(float lo, float hi) {
    ull d;
    asm("mov.b64 %0, {%1, %2};" : "=l"(d) : "f"(lo), "f"(hi));
    return d;
}
__device__ __forceinline__ void unpack2(ull v, float& lo, float& hi) {
    asm("mov.b64 {%0, %1}, %2;" : "=f"(lo), "=f"(hi) : "l"(v));
}

// ---------------------------------------------------------------------------
// Setup kernel A: combined categorical embedding table (512 combos x 32 ch)
// ---------------------------------------------------------------------------
__global__ void build_ct_kernel(const float* __restrict__ emb_dir,
                                const float* __restrict__ emb_type,
                                const float* __restrict__ emb_ring) {
    int idx = blockIdx.x * blockDim.x + threadIdx.x;
    if (idx >= 512 * 32) return;
    int l = idx & 31;
    int comb = idx >> 5;
    int ring = comb & 3;
    int type = (comb >> 2) & 15;
    int dir  = comb >> 6;
    g_ct[idx] = emb_dir[dir * 32 + l] + emb_type[type * 32 + l] + emb_ring[ring * 32 + l];
}

// ---------------------------------------------------------------------------
// Setup kernel B: PWL table for g(x) = rbf(x) @ rbf_W + rbf_b
// One thread per (interval i, channel-pair p). Stores (v(x_i), slope pair).
// ---------------------------------------------------------------------------
__global__ void build_tab_kernel(const float* __restrict__ rbf_W,
                                 const float* __restrict__ rbf_b) {
    int idx = blockIdx.x * blockDim.x + threadIdx.x;
    if (idx >= TAB_INTERVALS * 16) return;
    int p = idx & 15;       // channel pair: channels 2p, 2p+1
    int i = idx >> 4;       // interval
    float x0 = (float)i / TAB_SCALE;
    float x1 = (float)(i + 1) / TAB_SCALE;
    float v00 = rbf_b[2 * p], v01 = rbf_b[2 * p + 1];
    float v10 = v00, v11 = v01;
#pragma unroll
    for (int k = 0; k < NCEN; k++) {
        float c = 0.1f * (float)k;
        float w0 = rbf_W[k * 32 + 2 * p];
        float w1 = rbf_W[k * 32 + 2 * p + 1];
        float d0 = x0 - c, d1 = x1 - c;
        float e0 = expf(-RBF_GAMMA * d0 * d0);
        float e1 = expf(-RBF_GAMMA * d1 * d1);
        v00 = fmaf(e0, w0, v00);
        v01 = fmaf(e0, w1, v01);
        v10 = fmaf(e1, w0, v10);
        v11 = fmaf(e1, w1, v11);
    }
    g_tab[idx] = make_float4(v00, v01, v10 - v00, v11 - v01);
}

// ---------------------------------------------------------------------------
// Kernel 1: zero the aggregation buffer (we reuse d_out as agg scratch)
// ---------------------------------------------------------------------------
__global__ void zero_kernel(float4* __restrict__ p, int n4) {
    int i = blockIdx.x * blockDim.x + threadIdx.x;
    int stride = gridDim.x * blockDim.x;
    float4 z = make_float4(0.f, 0.f, 0.f, 0.f);
    for (; i < n4; i += stride) p[i] = z;
}

// ---------------------------------------------------------------------------
// Kernel 2: per-edge message + scatter. Warp per edge, lane l owns channels
// {2l, 2l+1}. No shuffles, no MUFU: table lookups + float2 gather + red.v2.
// ---------------------------------------------------------------------------
__global__ void edge_kernel(
    const float* __restrict__ atom,
    const int*   __restrict__ src,  const int* __restrict__ dst,
    const int*   __restrict__ rdir, const int* __restrict__ rtype, const int* __restrict__ rring,
    const int*   __restrict__ pdir, const int* __restrict__ ptype, const int* __restrict__ pring,
    const float* __restrict__ rlen, const float* __restrict__ plen,
    float* __restrict__ agg)
{
    const int l = threadIdx.x & 31;
    const int p = l & 15;                 // channel pair within half
    const bool upper = (l >= 16);         // owns channels 32..63 (the p - r half)
    const int warp = (blockIdx.x * blockDim.x + threadIdx.x) >> 5;
    const int nwarps = (gridDim.x * blockDim.x) >> 5;

    for (int e = warp; e < N_EDGES; e += nwarps) {
        const int s  = src[e];
        const int dn = dst[e];
        const int icr = (rdir[e] * 16 + rtype[e]) * 4 + rring[e];
        const int icp = (pdir[e] * 16 + ptype[e]) * 4 + pring[e];

        float xr = rlen[e] * TAB_SCALE;
        int   ir = min((int)xr, TAB_INTERVALS - 1);
        float fr = xr - (float)ir;
        float xp = plen[e] * TAB_SCALE;
        int   ip = min((int)xp, TAB_INTERVALS - 1);
        float fp_ = xp - (float)ip;

        // r-side embed for channels (2p, 2p+1)
        float2 ctr = *reinterpret_cast<const float2*>(&g_ct[icr * 32 + 2 * p]);
        float4 tr  = g_tab[ir * 16 + p];
        float re0 = ctr.x + fmaf(fr, tr.z, tr.x);
        float re1 = ctr.y + fmaf(fr, tr.w, tr.y);

        // p-side embed (used only by upper lanes, computed uniformly)
        float2 ctp = *reinterpret_cast<const float2*>(&g_ct[icp * 32 + 2 * p]);
        float4 tp  = g_tab[ip * 16 + p];
        float pe0 = ctp.x + fmaf(fp_, tp.z, tp.x);
        float pe1 = ctp.y + fmaf(fp_, tp.w, tp.y);

        // gather: channel (2l, 2l+1) of atom row (identical index math both halves)
        float2 a = *reinterpret_cast<const float2*>(&atom[(size_t)s * CD + 2 * l]);

        float add0 = upper ? (pe0 - re0) : re0;
        float add1 = upper ? (pe1 - re1) : re1;
        float v0 = a.x + add0;
        float v1 = a.y + add1;

        float* q = agg + (size_t)dn * CD + 2 * l;
        asm volatile("red.global.add.v2.f32 [%0], {%1,%2};"
                     :: "l"(q), "f"(v0), "f"(v1)
                     : "memory");
    }
}

// ---------------------------------------------------------------------------
// Kernel 3: per-node MLP, in place on the agg buffer.
// THREAD-per-node, broadcast LDS weights, packed fma.rn.f32x2.
// ---------------------------------------------------------------------------
#define W1T_STRIDE 68   // padded row stride (floats): kills STS conflicts, keeps 16B align

__global__ __launch_bounds__(128) void mlp_kernel(
    float* __restrict__ inout,           // [N_NODES, CD], agg in, out out
    const float* __restrict__ W1,        // [CD, HID]
    const float* __restrict__ b1,        // [HID]
    const float* __restrict__ W2,        // [HID, CD]
    const float* __restrict__ b2)        // [CD]
{
    extern __shared__ float sm[];
    float* sW1T = sm;                          // [HID][W1T_STRIDE] transposed W1
    float* sW2  = sW1T + HID * W1T_STRIDE;     // [HID][CD]
    float* sb1  = sW2 + HID * CD;              // [HID]
    float* sb2  = sb1 + HID;                   // [CD]

    const int tid = threadIdx.x;

    // Load W1 transposed: read coalesced (idx = j*HID + i), scatter to sW1T[i][j].
    for (int idx = tid; idx < CD * HID; idx += blockDim.x) {
        int j = idx >> 7;        // 0..63
        int i = idx & 127;       // 0..127
        sW1T[i * W1T_STRIDE + j] = W1[idx];
    }
    for (int idx = tid; idx < HID * CD; idx += blockDim.x) sW2[idx] = W2[idx];
    if (tid < HID) sb1[tid] = b1[tid];
    if (tid < CD)  sb2[tid] = b2[tid];
    __syncthreads();

    int n = blockIdx.x * blockDim.x + tid;
    if (n >= N_NODES) return;

    float* row = inout + (size_t)n * CD;

    // Load this node's 64 activations as 32 packed f32x2.
    ull a2[32];
    {
        const ulonglong2* ar = reinterpret_cast<const ulonglong2*>(row);
#pragma unroll
        for (int k = 0; k < 16; k++) {
            ulonglong2 v = ar[k];
            a2[2 * k]     = v.x;
            a2[2 * k + 1] = v.y;
        }
    }

    // Output accumulators init = b2 (bit-packed pairs straight from smem).
    ull o2[32];
    {
        const ulonglong2* bp = reinterpret_cast<const ulonglong2*>(sb2);
#pragma unroll
        for (int k = 0; k < 16; k++) {
            ulonglong2 v = bp[k];
            o2[2 * k]     = v.x;
            o2[2 * k + 1] = v.y;
        }
    }

    const ull z2 = pack2(0.f, 0.f);

#pragma unroll 4
    for (int i = 0; i < HID; i++) {
        // h_i = relu(b1[i] + sum_j a[j] * W1[j][i])  — pair over j
        const ulonglong2* w1r =
            reinterpret_cast<const ulonglong2*>(sW1T + i * W1T_STRIDE);
        ull acc0 = z2, acc1 = z2;
#pragma unroll
        for (int q = 0; q < 16; q++) {
            ulonglong2 w = w1r[q];                 // broadcast LDS.128
            acc0 = ffma2(a2[2 * q],     w.x, acc0);
            acc1 = ffma2(a2[2 * q + 1], w.y, acc1);
        }
        float l0, h0, l1, h1;
        unpack2(acc0, l0, h0);
        unpack2(acc1, l1, h1);
        float h = fmaxf((l0 + h0) + (l1 + h1) + sb1[i], 0.f);
        ull hh = pack2(h, h);

        // out[n] += h_i * W2[i][n]  — pair over n
        const ulonglong2* w2r =
            reinterpret_cast<const ulonglong2*>(sW2 + i * CD);
#pragma unroll
        for (int q = 0; q < 16; q++) {
            ulonglong2 w = w2r[q];                 // broadcast LDS.128
            o2[2 * q]     = ffma2(hh, w.x, o2[2 * q]);
            o2[2 * q + 1] = ffma2(hh, w.y, o2[2 * q + 1]);
        }
    }

    // Final relu + store.
    float4* outv = reinterpret_cast<float4*>(row);
#pragma unroll
    for (int k = 0; k < 16; k++) {
        float x0, x1, x2, x3;
        unpack2(o2[2 * k],     x0, x1);
        unpack2(o2[2 * k + 1], x2, x3);
        float4 r;
        r.x = fmaxf(x0, 0.f);
        r.y = fmaxf(x1, 0.f);
        r.z = fmaxf(x2, 0.f);
        r.w = fmaxf(x3, 0.f);
        outv[k] = r;
    }
}

// ---------------------------------------------------------------------------
// Launch
// Inputs (metadata order):
//  0 atom_repr [N,64] f32     1 src [E] i32      2 dst [E] i32
//  3 r_dir     4 r_type       5 r_ring           6 p_dir
//  7 p_type    8 p_ring       9 r_len f32       10 p_len f32
// 11 emb_dir [8,32]          12 emb_type [16,32] 13 emb_ring [4,32]
// 14 rbf_W [20,32]           15 rbf_b [32]
// 16 W1 [64,128]             17 b1 [128]
// 18 W2 [128,64]             19 b2 [64]
// Output: [N,64] f32
// ---------------------------------------------------------------------------
extern "C" void kernel_launch(void* const* d_in, const int* in_sizes, int n_in,
                              void* d_out, int out_size) {
    const float* atom     = (const float*)d_in[0];
    const int*   src      = (const int*)d_in[1];
    const int*   dst      = (const int*)d_in[2];
    const int*   rdir     = (const int*)d_in[3];
    const int*   rtype    = (const int*)d_in[4];
    const int*   rring    = (const int*)d_in[5];
    const int*   pdir     = (const int*)d_in[6];
    const int*   ptype    = (const int*)d_in[7];
    const int*   pring    = (const int*)d_in[8];
    const float* rlen     = (const float*)d_in[9];
    const float* plen     = (const float*)d_in[10];
    const float* emb_dir  = (const float*)d_in[11];
    const float* emb_type = (const float*)d_in[12];
    const float* emb_ring = (const float*)d_in[13];
    const float* rbf_W    = (const float*)d_in[14];
    const float* rbf_b    = (const float*)d_in[15];
    const float* W1       = (const float*)d_in[16];
    const float* b1       = (const float*)d_in[17];
    const float* W2       = (const float*)d_in[18];
    const float* b2       = (const float*)d_in[19];
    float* out = (float*)d_out;

    // 0) build lookup tables (tiny)
    build_ct_kernel<<<(512 * 32 + 255) / 256, 256>>>(emb_dir, emb_type, emb_ring);
    build_tab_kernel<<<(TAB_INTERVALS * 16 + 255) / 256, 256>>>(rbf_W, rbf_b);

    // 1) zero the agg buffer (= d_out)
    int n4 = (N_NODES * CD) / 4;
    zero_kernel<<<4096, 256>>>((float4*)out, n4);

    // 2) edge scatter (shuffle-free)
    edge_kernel<<<1480, 256>>>(atom, src, dst, rdir, rtype, rring,
                               pdir, ptype, pring, rlen, plen, out);

    // 3) node MLP (in place), thread-per-node
    size_t smem = (size_t)(HID * W1T_STRIDE + HID * CD + HID + CD) * sizeof(float);
    cudaFuncSetAttribute(mlp_kernel, cudaFuncAttributeMaxDynamicSharedMemorySize,
                         (int)smem);
    int blocks = (N_NODES + 127) / 128;
    mlp_kernel<<<blocks, 128, smem>>>(out, W1, b1, W2, b2);
}

// round 4
// speedup vs baseline: 1.9093x; 1.0279x over previous
#include <cuda_runtime.h>
#include <cuda_bf16.h>
#include <cstdint>

// Problem constants (fixed by the reference)
#define N_NODES 500000
#define N_EDGES 1000000
#define D       32
#define CD      64
#define HID     128
#define NCEN    20
#define RBF_GAMMA 10.0f

#define TAB_INTERVALS 2048        // PWL intervals over len in [0,2)
#define TAB_SCALE     1024.0f     // intervals per unit length

#define FULLMASK 0xffffffffu

typedef unsigned long long ull;

// ---- device-global precomputed tables (allowed scratch) --------------------
__device__ float  g_ct[512 * 32];              // combined cat embedding [(dir*16+type)*4+ring][ch]
__device__ float4 g_tab[TAB_INTERVALS * 16];   // PWL rbf: per (interval, ch-pair): (v0,v1,dv0,dv1)

// ---- packed f32x2 helpers (sm_103a) ---------------------------------------
__device__ __forceinline__ ull ffma2(ull a, ull b, ull c) {
    ull d;
    asm("fma.rn.f32x2 %0, %1, %2, %3;" : "=l"(d) : "l"(a), "l"(b), "l"(c));
    return d;
}
__device__ __forceinline__ ull pack2(float lo, float hi) {
    ull d;
    asm("mov.b64 %0, {%1, %2};" : "=l"(d) : "f"(lo), "f"(hi));
    return d;
}
__device__ __forceinline__ void unpack2(ull v, float& lo, float& hi) {
    asm("mov.b64 {%0, %1}, %2;" : "=f"(lo), "=f"(hi) : "l"(v));
}

// ---------------------------------------------------------------------------
// Setup kernel A: combined categorical embedding table (512 combos x 32 ch)
// ---------------------------------------------------------------------------
__global__ void build_ct_kernel(const float* __restrict__ emb_dir,
                                const float* __restrict__ emb_type,
                                const float* __restrict__ emb_ring) {
    int idx = blockIdx.x * blockDim.x + threadIdx.x;
    if (idx >= 512 * 32) return;
    int l = idx & 31;
    int comb = idx >> 5;
    int ring = comb & 3;
    int type = (comb >> 2) & 15;
    int dir  = comb >> 6;
    g_ct[idx] = emb_dir[dir * 32 + l] + emb_type[type * 32 + l] + emb_ring[ring * 32 + l];
}

// ---------------------------------------------------------------------------
// Setup kernel B: PWL table for g(x) = rbf(x) @ rbf_W + rbf_b
// ---------------------------------------------------------------------------
__global__ void build_tab_kernel(const float* __restrict__ rbf_W,
                                 const float* __restrict__ rbf_b) {
    int idx = blockIdx.x * blockDim.x + threadIdx.x;
    if (idx >= TAB_INTERVALS * 16) return;
    int p = idx & 15;       // channel pair: channels 2p, 2p+1
    int i = idx >> 4;       // interval
    float x0 = (float)i / TAB_SCALE;
    float x1 = (float)(i + 1) / TAB_SCALE;
    float v00 = rbf_b[2 * p], v01 = rbf_b[2 * p + 1];
    float v10 = v00, v11 = v01;
#pragma unroll
    for (int k = 0; k < NCEN; k++) {
        float c = 0.1f * (float)k;
        float w0 = rbf_W[k * 32 + 2 * p];
        float w1 = rbf_W[k * 32 + 2 * p + 1];
        float d0 = x0 - c, d1 = x1 - c;
        float e0 = expf(-RBF_GAMMA * d0 * d0);
        float e1 = expf(-RBF_GAMMA * d1 * d1);
        v00 = fmaf(e0, w0, v00);
        v01 = fmaf(e0, w1, v01);
        v10 = fmaf(e1, w0, v10);
        v11 = fmaf(e1, w1, v11);
    }
    g_tab[idx] = make_float4(v00, v01, v10 - v00, v11 - v01);
}

// ---------------------------------------------------------------------------
// Kernel 1: zero the aggregation buffer (we reuse d_out as agg scratch)
// ---------------------------------------------------------------------------
__global__ void zero_kernel(float4* __restrict__ p, int n4) {
    int i = blockIdx.x * blockDim.x + threadIdx.x;
    int stride = gridDim.x * blockDim.x;
    float4 z = make_float4(0.f, 0.f, 0.f, 0.f);
    for (; i < n4; i += stride) p[i] = z;
}

// ---------------------------------------------------------------------------
// Kernel 2: edge message + scatter. TWO edges per warp: lanes 0-15 handle
// edge e, lanes 16-31 edge e+1. Lane m (within group) owns channels 4m..4m+3
// -> one float4 gather + one red.global.add.v4.f32 per lane group.
// No shuffles, no MUFU.
// ---------------------------------------------------------------------------
__global__ void edge_kernel(
    const float* __restrict__ atom,
    const int*   __restrict__ src,  const int* __restrict__ dst,
    const int*   __restrict__ rdir, const int* __restrict__ rtype, const int* __restrict__ rring,
    const int*   __restrict__ pdir, const int* __restrict__ ptype, const int* __restrict__ pring,
    const float* __restrict__ rlen, const float* __restrict__ plen,
    float* __restrict__ agg)
{
    const int l = threadIdx.x & 31;
    const int g = l >> 4;                 // edge group within warp
    const int m = l & 15;                 // lane within group
    const bool upper = (m >= 8);          // owns channels 32..63 (the p-r half)
    const int cb = (4 * m) & 31;          // channel base within 32-wide embed
    const int pb = cb >> 1;               // pair base (even, 0..14)
    const int warp = (blockIdx.x * blockDim.x + threadIdx.x) >> 5;
    const int nwarps = (gridDim.x * blockDim.x) >> 5;

    for (int e = warp * 2 + g; e < N_EDGES; e += nwarps * 2) {
        const int s  = src[e];
        const int dn = dst[e];
        const int icr = (rdir[e] * 16 + rtype[e]) * 4 + rring[e];
        const int icp = (pdir[e] * 16 + ptype[e]) * 4 + pring[e];

        float xr = rlen[e] * TAB_SCALE;
        int   ir = min((int)xr, TAB_INTERVALS - 1);
        float fr = xr - (float)ir;
        float xp = plen[e] * TAB_SCALE;
        int   ip = min((int)xp, TAB_INTERVALS - 1);
        float fp_ = xp - (float)ip;

        float4 ctr = *reinterpret_cast<const float4*>(&g_ct[icr * 32 + cb]);
        float4 ctp = *reinterpret_cast<const float4*>(&g_ct[icp * 32 + cb]);
        float4 t0r = g_tab[ir * 16 + pb];
        float4 t1r = g_tab[ir * 16 + pb + 1];
        float4 t0p = g_tab[ip * 16 + pb];
        float4 t1p = g_tab[ip * 16 + pb + 1];

        float re0 = ctr.x + fmaf(fr, t0r.z, t0r.x);
        float re1 = ctr.y + fmaf(fr, t0r.w, t0r.y);
        float re2 = ctr.z + fmaf(fr, t1r.z, t1r.x);
        float re3 = ctr.w + fmaf(fr, t1r.w, t1r.y);

        float pe0 = ctp.x + fmaf(fp_, t0p.z, t0p.x);
        float pe1 = ctp.y + fmaf(fp_, t0p.w, t0p.y);
        float pe2 = ctp.z + fmaf(fp_, t1p.z, t1p.x);
        float pe3 = ctp.w + fmaf(fp_, t1p.w, t1p.y);

        float ad0 = upper ? (pe0 - re0) : re0;
        float ad1 = upper ? (pe1 - re1) : re1;
        float ad2 = upper ? (pe2 - re2) : re2;
        float ad3 = upper ? (pe3 - re3) : re3;

        // gather channels 4m..4m+3 of source row (4m spans both halves correctly)
        float4 a = *reinterpret_cast<const float4*>(&atom[(size_t)s * CD + 4 * m]);
        float v0 = a.x + ad0;
        float v1 = a.y + ad1;
        float v2 = a.z + ad2;
        float v3 = a.w + ad3;

        float* q = agg + (size_t)dn * CD + 4 * m;
        asm volatile("red.global.add.v4.f32 [%0], {%1,%2,%3,%4};"
                     :: "l"(q), "f"(v0), "f"(v1), "f"(v2), "f"(v3)
                     : "memory");
    }
}

// ---------------------------------------------------------------------------
// Kernel 3: per-node MLP, in place. TWO THREADS per node: even lane owns
// input/output channels 0..31, odd lane 32..63. One shfl.xor(1) per hidden
// unit combines stage-1 partials. ~95 live regs -> no spills. Weight panels
// in smem with 16B skew between even/odd panels (conflict-free dual-address
// LDS.128). Grid-stride (444 blocks) so weights are staged only 444 times.
// ---------------------------------------------------------------------------
#define PANEL (HID * 32 + 4)   // 4100 floats per panel incl. 16B skew pad

__global__ __launch_bounds__(128) void mlp_kernel(
    float* __restrict__ inout,           // [N_NODES, CD], agg in, out out
    const float* __restrict__ W1,        // [CD, HID]
    const float* __restrict__ b1,        // [HID]
    const float* __restrict__ W2,        // [HID, CD]
    const float* __restrict__ b2)        // [CD]
{
    extern __shared__ float sm[];
    float* sW1E = sm;                    // [128][32]: W1[j][i], j<32  (indexed [i*32+j])
    float* sW1O = sW1E + PANEL;          // j>=32
    float* sW2E = sW1O + PANEL;          // [128][32]: W2[i][c], c<32 (indexed [i*32+c])
    float* sW2O = sW2E + PANEL;          // c>=32
    float* sb1  = sW2O + PANEL;          // [128]
    float* sb2  = sb1 + HID;             // [64]

    const int tid = threadIdx.x;

    // W1 [64][128] j-major -> split panels, transposed to i-major rows of 32.
    for (int idx = tid; idx < CD * HID; idx += blockDim.x) {
        int j = idx >> 7;        // 0..63
        int i = idx & 127;       // 0..127
        float v = W1[idx];
        if (j < 32) sW1E[i * 32 + j] = v;
        else        sW1O[i * 32 + (j - 32)] = v;
    }
    // W2 [128][64] i-major -> split halves.
    for (int idx = tid; idx < HID * CD; idx += blockDim.x) {
        int i = idx >> 6;        // 0..127
        int c = idx & 63;        // 0..63
        float v = W2[idx];
        if (c < 32) sW2E[i * 32 + c] = v;
        else        sW2O[i * 32 + (c - 32)] = v;
    }
    if (tid < HID) sb1[tid] = b1[tid];
    if (tid < CD)  sb2[tid] = b2[tid];
    __syncthreads();

    const int half = tid & 1;            // 0: channels 0..31, 1: channels 32..63
    const int slot = tid >> 1;           // node slot within block (0..63)
    const float* w1p = half ? sW1O : sW1E;
    const float* w2p = half ? sW2O : sW2E;

    for (long n = (long)blockIdx.x * 64 + slot; n < N_NODES;
         n += (long)gridDim.x * 64) {
        float* row = inout + n * CD + half * 32;   // this thread's 32 channels

        // activations (my half of the row): 32 floats = 16 packed pairs
        ull a[16];
        {
            const ulonglong2* ar = reinterpret_cast<const ulonglong2*>(row);
#pragma unroll
            for (int k = 0; k < 8; k++) {
                ulonglong2 v = ar[k];
                a[2 * k]     = v.x;
                a[2 * k + 1] = v.y;
            }
        }
        // output accumulators init = my half of b2
        ull o[16];
        {
            const ulonglong2* bp =
                reinterpret_cast<const ulonglong2*>(sb2 + half * 32);
#pragma unroll
            for (int k = 0; k < 8; k++) {
                ulonglong2 v = bp[k];
                o[2 * k]     = v.x;
                o[2 * k + 1] = v.y;
            }
        }

#pragma unroll 2
        for (int i = 0; i < HID; i++) {
            // partial_i = sum over my 32 j of a[j]*W1[j][i]
            const ulonglong2* w1r =
                reinterpret_cast<const ulonglong2*>(w1p + i * 32);
            ull acc0 = 0ull, acc1 = 0ull;
#pragma unroll
            for (int q = 0; q < 4; q++) {
                ulonglong2 wA = w1r[2 * q];
                ulonglong2 wB = w1r[2 * q + 1];
                acc0 = ffma2(a[4 * q],     wA.x, acc0);
                acc1 = ffma2(a[4 * q + 1], wA.y, acc1);
                acc0 = ffma2(a[4 * q + 2], wB.x, acc0);
                acc1 = ffma2(a[4 * q + 3], wB.y, acc1);
            }
            float x0, x1, y0, y1;
            unpack2(acc0, x0, x1);
            unpack2(acc1, y0, y1);
            float part = (x0 + y0) + (x1 + y1);
            float h = part + __shfl_xor_sync(FULLMASK, part, 1) + sb1[i];
            h = fmaxf(h, 0.f);
            ull hh = pack2(h, h);

            // out[my 32 c] += h * W2[i][c]
            const ulonglong2* w2r =
                reinterpret_cast<const ulonglong2*>(w2p + i * 32);
#pragma unroll
            for (int q = 0; q < 8; q++) {
                ulonglong2 w = w2r[q];
                o[2 * q]     = ffma2(hh, w.x, o[2 * q]);
                o[2 * q + 1] = ffma2(hh, w.y, o[2 * q + 1]);
            }
        }

        // relu + store my half
        float4* outv = reinterpret_cast<float4*>(row);
#pragma unroll
        for (int k = 0; k < 8; k++) {
            float x0, x1, x2, x3;
            unpack2(o[2 * k],     x0, x1);
            unpack2(o[2 * k + 1], x2, x3);
            float4 r;
            r.x = fmaxf(x0, 0.f);
            r.y = fmaxf(x1, 0.f);
            r.z = fmaxf(x2, 0.f);
            r.w = fmaxf(x3, 0.f);
            outv[k] = r;
        }
    }
}

// ---------------------------------------------------------------------------
// Launch
// Inputs (metadata order):
//  0 atom_repr [N,64] f32     1 src [E] i32      2 dst [E] i32
//  3 r_dir     4 r_type       5 r_ring           6 p_dir
//  7 p_type    8 p_ring       9 r_len f32       10 p_len f32
// 11 emb_dir [8,32]          12 emb_type [16,32] 13 emb_ring [4,32]
// 14 rbf_W [20,32]           15 rbf_b [32]
// 16 W1 [64,128]             17 b1 [128]
// 18 W2 [128,64]             19 b2 [64]
// Output: [N,64] f32
// ---------------------------------------------------------------------------
extern "C" void kernel_launch(void* const* d_in, const int* in_sizes, int n_in,
                              void* d_out, int out_size) {
    const float* atom     = (const float*)d_in[0];
    const int*   src      = (const int*)d_in[1];
    const int*   dst      = (const int*)d_in[2];
    const int*   rdir     = (const int*)d_in[3];
    const int*   rtype    = (const int*)d_in[4];
    const int*   rring    = (const int*)d_in[5];
    const int*   pdir     = (const int*)d_in[6];
    const int*   ptype    = (const int*)d_in[7];
    const int*   pring    = (const int*)d_in[8];
    const float* rlen     = (const float*)d_in[9];
    const float* plen     = (const float*)d_in[10];
    const float* emb_dir  = (const float*)d_in[11];
    const float* emb_type = (const float*)d_in[12];
    const float* emb_ring = (const float*)d_in[13];
    const float* rbf_W    = (const float*)d_in[14];
    const float* rbf_b    = (const float*)d_in[15];
    const float* W1       = (const float*)d_in[16];
    const float* b1       = (const float*)d_in[17];
    const float* W2       = (const float*)d_in[18];
    const float* b2       = (const float*)d_in[19];
    float* out = (float*)d_out;

    // 0) build lookup tables (tiny)
    build_ct_kernel<<<(512 * 32 + 255) / 256, 256>>>(emb_dir, emb_type, emb_ring);
    build_tab_kernel<<<(TAB_INTERVALS * 16 + 255) / 256, 256>>>(rbf_W, rbf_b);

    // 1) zero the agg buffer (= d_out)
    int n4 = (N_NODES * CD) / 4;
    zero_kernel<<<4096, 256>>>((float4*)out, n4);

    // 2) edge scatter (2 edges/warp, 16-lane red.v4)
    edge_kernel<<<2048, 256>>>(atom, src, dst, rdir, rtype, rring,
                               pdir, ptype, pring, rlen, plen, out);

    // 3) node MLP (in place), 2 threads per node, grid-stride
    size_t smem = (size_t)(4 * PANEL + HID + CD) * sizeof(float);
    cudaFuncSetAttribute(mlp_kernel, cudaFuncAttributeMaxDynamicSharedMemorySize,
                         (int)smem);
    mlp_kernel<<<444, 128, smem>>>(out, W1, b1, W2, b2);
}